// round 13
// baseline (speedup 1.0000x reference)
#include <cuda_runtime.h>
#include <cuda_fp16.h>
#include <cuda_bf16.h>
#include <cstdint>

// ============================================================================
// int8 GEMM + dequant:  out[m,n] = f32( fp16_round( acc[m,n] * a_s[m] * w_s[n] ) )
//   M=8192 (4*2048), K=4096, N=4096, acc = int32 sum_k a*w
//
// I/O layer (validated round by round):
//   - inputs identified by element/byte counts (order-independent)
//   - matrix dtype probed on device (packed int8 / int32 / f32 / bf16 / f16)
//   - scale dtype probed (f32 / bf16 / f16)
//   - OUTPUT: float32 buffer (harness materializes fp16 as f32); values
//     rounded through fp16 to match reference .astype(float16) bit-exactly
// Compute: plain dp4a GEMM (known-good path), CTA 128x128x64.
//
// (Round 10 was an infra failure — this resubmits the untested R7 kernel
//  unchanged to get a clean verdict on the output-dtype hypothesis.)
// ============================================================================

namespace {

constexpr int MDIM = 8192;
constexpr int NDIM = 4096;
constexpr int KDIM = 4096;
constexpr int BM = 128, BN = 128, BK = 64;
constexpr int NKC = KDIM / BK;   // 64

__device__ int g_modeA;    // matrices: 0=int8 packed, 1=int32, 2=f32, 3=bf16, 4=f16
__device__ int g_modeW;
__device__ int g_modeAs;   // scales: 0=f32, 1=bf16, 2=f16
__device__ int g_modeWs;

// ---------------- dtype probes ----------------
__global__ void probe_matrix(const uint8_t* __restrict__ buf, int which) {
  __shared__ int ok[4];
  const int tid = threadIdx.x;
  if (tid < 4) ok[tid] = 1;
  __syncthreads();
  for (int i = tid; i < 1024; i += blockDim.x) {
    const int vi = ((const int*)buf)[i];
    if (vi < -128 || vi > 127) ok[0] = 0;
    const float vf = ((const float*)buf)[i];
    if (!(vf >= -128.f && vf <= 127.f && floorf(vf) == vf)) ok[1] = 0;
    const float vb = __bfloat162float(((const __nv_bfloat16*)buf)[i]);
    if (!(vb >= -128.f && vb <= 127.f && floorf(vb) == vb)) ok[2] = 0;
    const float vh = __half2float(((const __half*)buf)[i]);
    if (!(vh >= -128.f && vh <= 127.f && floorf(vh) == vh)) ok[3] = 0;
  }
  __syncthreads();
  if (tid == 0) {
    const int mode = ok[0] ? 1 : ok[1] ? 2 : ok[2] ? 3 : ok[3] ? 4 : 0;
    if (which == 0) g_modeA = mode; else g_modeW = mode;
  }
}

__global__ void probe_scale(const uint8_t* __restrict__ buf, int which) {
  __shared__ int ok[3];
  const int tid = threadIdx.x;
  if (tid < 3) ok[tid] = 1;
  __syncthreads();
  // scales are (u+0.5)*0.01 in (0.005, 0.015)
  for (int i = tid; i < 512; i += blockDim.x) {
    const float vf = ((const float*)buf)[i];
    if (!(vf > 1e-4f && vf < 1.0f)) ok[0] = 0;
    const float vb = __bfloat162float(((const __nv_bfloat16*)buf)[i]);
    if (!(vb > 1e-4f && vb < 1.0f)) ok[1] = 0;
    const float vh = __half2float(((const __half*)buf)[i]);
    if (!(vh > 1e-4f && vh < 1.0f)) ok[2] = 0;
  }
  __syncthreads();
  if (tid == 0) {
    const int mode = ok[0] ? 0 : ok[1] ? 1 : 2;
    if (which == 0) g_modeAs = mode; else g_modeWs = mode;
  }
}

__device__ __forceinline__ float get_scale(const uint8_t* base, int idx, int mode) {
  if (mode == 0) return ((const float*)base)[idx];
  if (mode == 1) return __bfloat162float(((const __nv_bfloat16*)base)[idx]);
  return __half2float(((const __half*)base)[idx]);
}

// pack 4 consecutive logical int8 elements starting at element index e
__device__ __forceinline__ uint32_t pack4(const uint8_t* base, size_t e, int mode) {
  if (mode == 0) {
    return *(const uint32_t*)(base + e);
  } else if (mode == 1) {
    const int* p = (const int*)base + e;
    return (uint32_t)(p[0] & 0xFF) | ((uint32_t)(p[1] & 0xFF) << 8)
         | ((uint32_t)(p[2] & 0xFF) << 16) | ((uint32_t)(p[3] & 0xFF) << 24);
  } else if (mode == 2) {
    const float* p = (const float*)base + e;
    const int a = (int)p[0], b = (int)p[1], c = (int)p[2], d = (int)p[3];
    return (uint32_t)(a & 0xFF) | ((uint32_t)(b & 0xFF) << 8)
         | ((uint32_t)(c & 0xFF) << 16) | ((uint32_t)(d & 0xFF) << 24);
  } else if (mode == 3) {
    const __nv_bfloat16* p = (const __nv_bfloat16*)base + e;
    const int a = (int)__bfloat162float(p[0]), b = (int)__bfloat162float(p[1]);
    const int c = (int)__bfloat162float(p[2]), d = (int)__bfloat162float(p[3]);
    return (uint32_t)(a & 0xFF) | ((uint32_t)(b & 0xFF) << 8)
         | ((uint32_t)(c & 0xFF) << 16) | ((uint32_t)(d & 0xFF) << 24);
  } else {
    const __half* p = (const __half*)base + e;
    const int a = (int)__half2float(p[0]), b = (int)__half2float(p[1]);
    const int c = (int)__half2float(p[2]), d = (int)__half2float(p[3]);
    return (uint32_t)(a & 0xFF) | ((uint32_t)(b & 0xFF) << 8)
         | ((uint32_t)(c & 0xFF) << 16) | ((uint32_t)(d & 0xFF) << 24);
  }
}

__global__ void __launch_bounds__(256)
dp4a_gemm(const uint8_t* __restrict__ A,
          const uint8_t* __restrict__ As,
          const uint8_t* __restrict__ W,
          const uint8_t* __restrict__ Ws,
          float*         __restrict__ Out)
{
  __shared__ int8_t sa [BM][68];   // A tile, k-contiguous, +4 pad
  __shared__ int8_t swt[BN][68];   // W tile transposed, k-contiguous

  const int tid = threadIdx.x;
  const int tn  = tid & 15;
  const int tm  = tid >> 4;
  const int m0  = blockIdx.y * BM;
  const int n0  = blockIdx.x * BN;
  const int mA  = g_modeA;
  const int mW  = g_modeW;

  int acc[8][8];
  #pragma unroll
  for (int i = 0; i < 8; i++)
    #pragma unroll
    for (int j = 0; j < 8; j++) acc[i][j] = 0;

  const int kq = tid >> 5;   // 0..7   (4-k-row quad)
  const int ng = tid & 31;   // 0..31  (4-n-col group)

  for (int kc = 0; kc < NKC; kc++) {
    __syncthreads();

    // ---- A tile: 128 rows x 64 elements ----
    #pragma unroll
    for (int rep = 0; rep < 2; rep++) {
      const int idx = tid + 256 * rep;        // 0..511
      const int row = idx >> 2;               // 0..127
      const int c   = idx & 3;                // 16-element chunk
      const size_t e = (size_t)(m0 + row) * KDIM + kc * BK + c * 16;
      uint32_t* d = (uint32_t*)&sa[row][c * 16];
      #pragma unroll
      for (int w4 = 0; w4 < 4; w4++) d[w4] = pack4(A, e + w4 * 4, mA);
    }

    // ---- W tile: 64 k-rows x 128 n, transposed in registers ----
    #pragma unroll
    for (int rep = 0; rep < 2; rep++) {
      uint32_t w[4];
      #pragma unroll
      for (int i = 0; i < 4; i++)
        w[i] = pack4(W, (size_t)(kc * BK + rep * 32 + kq * 4 + i) * NDIM + n0 + ng * 4, mW);
      #pragma unroll
      for (int c = 0; c < 4; c++) {
        const uint32_t tw = ((w[0] >> (8 * c)) & 0xFF)
                          | (((w[1] >> (8 * c)) & 0xFF) << 8)
                          | (((w[2] >> (8 * c)) & 0xFF) << 16)
                          | (((w[3] >> (8 * c)) & 0xFF) << 24);
        const int kw = rep * 8 + kq;
        *(uint32_t*)&swt[ng * 4 + c][kw * 4] = tw;
      }
    }
    __syncthreads();

    // ---- compute: 16 k-words x 64 dp4a ----
    #pragma unroll
    for (int kw = 0; kw < 16; kw++) {
      int aw[8], bw[8];
      #pragma unroll
      for (int mi = 0; mi < 8; mi++)
        aw[mi] = *(const int*)&sa[tm + mi * 16][kw * 4];
      #pragma unroll
      for (int ni = 0; ni < 8; ni++)
        bw[ni] = *(const int*)&swt[tn + ni * 16][kw * 4];
      #pragma unroll
      for (int mi = 0; mi < 8; mi++)
        #pragma unroll
        for (int ni = 0; ni < 8; ni++)
          acc[mi][ni] = __dp4a(aw[mi], bw[ni], acc[mi][ni]);
    }
  }

  // ---- epilogue: dequant (reference multiply order), fp16-round, f32 store ----
  const int mAs = g_modeAs, mWs = g_modeWs;
  float asf[8], wsf[8];
  #pragma unroll
  for (int mi = 0; mi < 8; mi++) asf[mi] = get_scale(As, m0 + tm + mi * 16, mAs);
  #pragma unroll
  for (int ni = 0; ni < 8; ni++) wsf[ni] = get_scale(Ws, n0 + tn + ni * 16, mWs);

  #pragma unroll
  for (int mi = 0; mi < 8; mi++) {
    const size_t rb = (size_t)(m0 + tm + mi * 16) * NDIM + n0;
    #pragma unroll
    for (int ni = 0; ni < 8; ni++) {
      const float v = ((float)acc[mi][ni] * asf[mi]) * wsf[ni];
      Out[rb + tn + ni * 16] = __half2float(__float2half(v));   // match astype(fp16)
    }
  }
}

} // namespace

extern "C" void kernel_launch(void* const* d_in, const int* in_sizes, int n_in,
                              void* d_out, int out_size) {
  // defaults = reference dict order
  const uint8_t* A  = (const uint8_t*)d_in[0];
  const uint8_t* As = (const uint8_t*)d_in[1];
  const uint8_t* W  = (const uint8_t*)d_in[2];
  const uint8_t* Ws = (const uint8_t*)d_in[3];

  // identify by count (element counts or byte counts, any ordering)
  for (int i = 0; i < n_in; i++) {
    const long long s = in_sizes[i];
    switch (s) {
      case 33554432LL: case 134217728LL: A  = (const uint8_t*)d_in[i]; break; // 8192*4096
      case 16777216LL: case 67108864LL:  W  = (const uint8_t*)d_in[i]; break; // 4096*4096
      case 8192LL:     case 32768LL:     As = (const uint8_t*)d_in[i]; break; // 8192 scales
      case 4096LL:     case 16384LL:     Ws = (const uint8_t*)d_in[i]; break; // 4096 scales
      default: break;
    }
  }

  probe_matrix<<<1, 128>>>(A, 0);
  probe_matrix<<<1, 128>>>(W, 1);
  probe_scale<<<1, 128>>>(As, 0);
  probe_scale<<<1, 128>>>(Ws, 1);

  dim3 grid(NDIM / BN, MDIM / BM);   // 32 x 64
  dp4a_gemm<<<grid, 256>>>(A, As, W, Ws, (float*)d_out);
}

// round 14
// speedup vs baseline: 2.0776x; 2.0776x over previous
#include <cuda_runtime.h>
#include <cuda_fp16.h>
#include <cuda_bf16.h>
#include <cstdint>

// ============================================================================
// int8 GEMM + dequant:  out[m,n] = f32( fp16_round( acc * a_s[m] * w_s[n] ) )
//   M=8192, K=4096, N=4096
//
// Validated I/O layer (R13 pass, rel_err=0):
//   - inputs identified by element/byte counts
//   - matrix/scale dtypes probed on device
//   - output: f32 buffer, values rounded through fp16
//
// New this round:
//   - repack kernels normalize A -> packed int8 g_A, W -> transposed packed
//     int8 g_Wt (mode-independent); ~40us
//   - tensor-core GEMM: mma.sync.m16n8k32.s8, CTA 256x128x128, 3-stage
//     cp.async (144KB dynamic smem), swizzled ldmatrix, 8 warps of 64x64
//   - dp4a kernel kept as fallback if the smem attribute opt-in fails
// ============================================================================

namespace {

constexpr int MDIM = 8192;
constexpr int NDIM = 4096;
constexpr int KDIM = 4096;

__device__ int g_modeA;    // 0=int8 packed, 1=int32, 2=f32, 3=bf16, 4=f16
__device__ int g_modeW;
__device__ int g_modeAs;   // 0=f32, 1=bf16, 2=f16
__device__ int g_modeWs;

__device__ int8_t g_A [(size_t)MDIM * KDIM];   // 32 MB packed A
__device__ int8_t g_Wt[(size_t)NDIM * KDIM];   // 16 MB packed W^T (n-major, k-contig)

// ---------------- dtype probes ----------------
__global__ void probe_matrix(const uint8_t* __restrict__ buf, int which) {
  __shared__ int ok[4];
  const int tid = threadIdx.x;
  if (tid < 4) ok[tid] = 1;
  __syncthreads();
  for (int i = tid; i < 1024; i += blockDim.x) {
    const int vi = ((const int*)buf)[i];
    if (vi < -128 || vi > 127) ok[0] = 0;
    const float vf = ((const float*)buf)[i];
    if (!(vf >= -128.f && vf <= 127.f && floorf(vf) == vf)) ok[1] = 0;
    const float vb = __bfloat162float(((const __nv_bfloat16*)buf)[i]);
    if (!(vb >= -128.f && vb <= 127.f && floorf(vb) == vb)) ok[2] = 0;
    const float vh = __half2float(((const __half*)buf)[i]);
    if (!(vh >= -128.f && vh <= 127.f && floorf(vh) == vh)) ok[3] = 0;
  }
  __syncthreads();
  if (tid == 0) {
    const int mode = ok[0] ? 1 : ok[1] ? 2 : ok[2] ? 3 : ok[3] ? 4 : 0;
    if (which == 0) g_modeA = mode; else g_modeW = mode;
  }
}

__global__ void probe_scale(const uint8_t* __restrict__ buf, int which) {
  __shared__ int ok[3];
  const int tid = threadIdx.x;
  if (tid < 3) ok[tid] = 1;
  __syncthreads();
  for (int i = tid; i < 512; i += blockDim.x) {
    const float vf = ((const float*)buf)[i];
    if (!(vf > 1e-4f && vf < 1.0f)) ok[0] = 0;
    const float vb = __bfloat162float(((const __nv_bfloat16*)buf)[i]);
    if (!(vb > 1e-4f && vb < 1.0f)) ok[1] = 0;
    const float vh = __half2float(((const __half*)buf)[i]);
    if (!(vh > 1e-4f && vh < 1.0f)) ok[2] = 0;
  }
  __syncthreads();
  if (tid == 0) {
    const int mode = ok[0] ? 0 : ok[1] ? 1 : 2;
    if (which == 0) g_modeAs = mode; else g_modeWs = mode;
  }
}

__device__ __forceinline__ float get_scale(const uint8_t* base, int idx, int mode) {
  if (mode == 0) return ((const float*)base)[idx];
  if (mode == 1) return __bfloat162float(((const __nv_bfloat16*)base)[idx]);
  return __half2float(((const __half*)base)[idx]);
}
__device__ __forceinline__ int8_t get_i8(const uint8_t* base, size_t e, int mode) {
  if (mode == 0) return ((const int8_t*)base)[e];
  if (mode == 1) return (int8_t)((const int*)base)[e];
  if (mode == 2) return (int8_t)(int)((const float*)base)[e];
  if (mode == 3) return (int8_t)(int)__bfloat162float(((const __nv_bfloat16*)base)[e]);
  return (int8_t)(int)__half2float(((const __half*)base)[e]);
}
__device__ __forceinline__ uint32_t pack4(const uint8_t* base, size_t e, int mode) {
  if (mode == 0) return *(const uint32_t*)(base + e);
  uint32_t r = 0;
  #pragma unroll
  for (int i = 0; i < 4; i++)
    r |= ((uint32_t)(uint8_t)get_i8(base, e + i, mode)) << (8 * i);
  return r;
}

// ---------------- repack kernels ----------------
__global__ void __launch_bounds__(256) repack_A(const uint8_t* __restrict__ A) {
  const int mode = g_modeA;
  const size_t idx = (size_t)blockIdx.x * 256 + threadIdx.x;   // word index
  ((uint32_t*)g_A)[idx] = pack4(A, idx * 4, mode);
}

__global__ void __launch_bounds__(256) repack_Wt(const uint8_t* __restrict__ W) {
  __shared__ int8_t tile[128][132];
  const int mode = g_modeW;
  const int n0 = blockIdx.x * 128;
  const int k0 = blockIdx.y * 128;
  const int tid = threadIdx.x;
  for (int idx = tid; idx < 128 * 128; idx += 256) {
    const int k = idx >> 7, n = idx & 127;
    tile[k][n] = get_i8(W, (size_t)(k0 + k) * NDIM + n0 + n, mode);
  }
  __syncthreads();
  for (int idx = tid; idx < 128 * 32; idx += 256) {
    const int n = idx >> 5, kw = idx & 31;
    const uint32_t v = (uint32_t)(uint8_t)tile[kw * 4 + 0][n]
                     | ((uint32_t)(uint8_t)tile[kw * 4 + 1][n] << 8)
                     | ((uint32_t)(uint8_t)tile[kw * 4 + 2][n] << 16)
                     | ((uint32_t)(uint8_t)tile[kw * 4 + 3][n] << 24);
    *(uint32_t*)(g_Wt + (size_t)(n0 + n) * KDIM + k0 + kw * 4) = v;
  }
}

// ---------------- tensor-core GEMM ----------------
constexpr int BM = 256, BN = 128, BK = 128;
constexpr int STAGES = 3;
constexpr int NKI = KDIM / BK;            // 32
constexpr int ASTAGE = BM * BK;           // 32768
constexpr int BSTAGE = BN * BK;           // 16384
constexpr int STAGE  = ASTAGE + BSTAGE;   // 49152
constexpr int SMEM_TOTAL = STAGES * STAGE; // 147456

__device__ __forceinline__ uint32_t smem_u32(const void* p) {
  uint32_t a;
  asm("{ .reg .u64 t; cvta.to.shared.u64 t, %1; cvt.u32.u64 %0, t; }"
      : "=r"(a) : "l"(p));
  return a;
}
__device__ __forceinline__ void cp16(uint32_t s, const void* g) {
  asm volatile("cp.async.cg.shared.global [%0], [%1], 16;" :: "r"(s), "l"(g) : "memory");
}
__device__ __forceinline__ void cp_commit() {
  asm volatile("cp.async.commit_group;" ::: "memory");
}
__device__ __forceinline__ void cp_wait2() {
  asm volatile("cp.async.wait_group 2;" ::: "memory");
}
__device__ __forceinline__ void ldm4(uint32_t* r, uint32_t a) {
  asm volatile("ldmatrix.sync.aligned.m8n8.x4.shared.b16 {%0,%1,%2,%3}, [%4];"
               : "=r"(r[0]), "=r"(r[1]), "=r"(r[2]), "=r"(r[3]) : "r"(a));
}
__device__ __forceinline__ void mma_s8(int* d, const uint32_t* a, const uint32_t* b) {
  asm volatile(
      "mma.sync.aligned.m16n8k32.row.col.s32.s8.s8.s32 "
      "{%0,%1,%2,%3}, {%4,%5,%6,%7}, {%8,%9}, {%0,%1,%2,%3};"
      : "+r"(d[0]), "+r"(d[1]), "+r"(d[2]), "+r"(d[3])
      : "r"(a[0]), "r"(a[1]), "r"(a[2]), "r"(a[3]), "r"(b[0]), "r"(b[1]));
}

__global__ void __launch_bounds__(256, 1)
int8_gemm_mma(const uint8_t* __restrict__ As,
              const uint8_t* __restrict__ Ws,
              float*         __restrict__ Out)
{
  extern __shared__ uint8_t smem[];
  const uint32_t sb = smem_u32(smem);
  const int tid  = threadIdx.x;
  const int wid  = tid >> 5;
  const int lane = tid & 31;

  const int m0 = blockIdx.y * BM;
  const int n0 = blockIdx.x * BN;
  const int mw = (wid >> 1) * 64;
  const int nw = (wid & 1)  * 64;

  // producer: 16B chunk 0..7, base row 0..31
  const int pc = tid & 7;
  const int pr = tid >> 3;
  const int8_t* gA = g_A  + (size_t)(m0 + pr) * KDIM + pc * 16;
  const int8_t* gB = g_Wt + (size_t)(n0 + pr) * KDIM + pc * 16;

  auto load_stage = [&](int ki, int slot) {
    const uint32_t sa = sb + slot * STAGE;
    #pragma unroll
    for (int j = 0; j < 8; j++) {
      const int r = pr + 32 * j;
      cp16(sa + r * 128 + (((pc ^ (r & 7)) & 7) << 4),
           gA + ki * BK + (size_t)(32 * j) * KDIM);
    }
    const uint32_t sB = sa + ASTAGE;
    #pragma unroll
    for (int j = 0; j < 4; j++) {
      const int r = pr + 32 * j;
      cp16(sB + r * 128 + (((pc ^ (r & 7)) & 7) << 4),
           gB + ki * BK + (size_t)(32 * j) * KDIM);
    }
  };

  #pragma unroll
  for (int s = 0; s < STAGES - 1; s++) { load_stage(s, s); cp_commit(); }

  int acc[4][8][4];
  #pragma unroll
  for (int mf = 0; mf < 4; mf++)
    #pragma unroll
    for (int nf = 0; nf < 8; nf++)
      #pragma unroll
      for (int i = 0; i < 4; i++) acc[mf][nf][i] = 0;

  const int lrow  = lane & 15;
  const int lchnk = lane >> 4;

  for (int ki = 0; ki < NKI; ki++) {
    if (ki + STAGES - 1 < NKI)
      load_stage(ki + STAGES - 1, (ki + STAGES - 1) % STAGES);
    cp_commit();          // committed every iter -> uniform group counting
    cp_wait2();           // stage ki complete (2 newer groups pending)
    __syncthreads();

    const uint32_t abase = sb + (ki % STAGES) * STAGE;
    const uint32_t bbase = abase + ASTAGE;

    #pragma unroll
    for (int ks = 0; ks < 4; ks++) {
      uint32_t af[4][4];
      #pragma unroll
      for (int mf = 0; mf < 4; mf++) {
        const int r = mw + mf * 16 + lrow;
        const int c = ks * 2 + lchnk;
        ldm4(af[mf], abase + r * 128 + (((c ^ (r & 7)) & 7) << 4));
      }
      uint32_t bf[8][2];
      #pragma unroll
      for (int nf2 = 0; nf2 < 4; nf2++) {
        uint32_t r4[4];
        const int r = nw + nf2 * 16 + lrow;
        const int c = ks * 2 + lchnk;
        ldm4(r4, bbase + r * 128 + (((c ^ (r & 7)) & 7) << 4));
        bf[2 * nf2][0]     = r4[0]; bf[2 * nf2][1]     = r4[2];
        bf[2 * nf2 + 1][0] = r4[1]; bf[2 * nf2 + 1][1] = r4[3];
      }
      #pragma unroll
      for (int mf = 0; mf < 4; mf++)
        #pragma unroll
        for (int nf = 0; nf < 8; nf++)
          mma_s8(acc[mf][nf], af[mf], bf[nf]);
    }
    __syncthreads();
  }

  // epilogue: dequant (reference order), fp16-round, f32 store
  const int mAs = g_modeAs, mWs = g_modeWs;
  float ws[8][2];
  #pragma unroll
  for (int nf = 0; nf < 8; nf++) {
    const int c = n0 + nw + nf * 8 + (lane & 3) * 2;
    ws[nf][0] = get_scale(Ws, c,     mWs);
    ws[nf][1] = get_scale(Ws, c + 1, mWs);
  }
  #pragma unroll
  for (int mf = 0; mf < 4; mf++) {
    const int r = m0 + mw + mf * 16 + (lane >> 2);
    const float as0 = get_scale(As, r,     mAs);
    const float as1 = get_scale(As, r + 8, mAs);
    float* out0 = Out + (size_t)r * NDIM + n0 + nw + (lane & 3) * 2;
    float* out1 = out0 + (size_t)8 * NDIM;
    #pragma unroll
    for (int nf = 0; nf < 8; nf++) {
      float2 v0, v1;
      v0.x = __half2float(__float2half(((float)acc[mf][nf][0] * as0) * ws[nf][0]));
      v0.y = __half2float(__float2half(((float)acc[mf][nf][1] * as0) * ws[nf][1]));
      v1.x = __half2float(__float2half(((float)acc[mf][nf][2] * as1) * ws[nf][0]));
      v1.y = __half2float(__float2half(((float)acc[mf][nf][3] * as1) * ws[nf][1]));
      *(float2*)(out0 + nf * 8) = v0;
      *(float2*)(out1 + nf * 8) = v1;
    }
  }
}

// ---------------- dp4a fallback (known-good R13 path) ----------------
__global__ void __launch_bounds__(256)
dp4a_gemm(const uint8_t* __restrict__ A,
          const uint8_t* __restrict__ As,
          const uint8_t* __restrict__ W,
          const uint8_t* __restrict__ Ws,
          float*         __restrict__ Out)
{
  __shared__ int8_t sa [128][68];
  __shared__ int8_t swt[128][68];
  const int tid = threadIdx.x;
  const int tn  = tid & 15;
  const int tm  = tid >> 4;
  const int m0  = blockIdx.y * 128;
  const int n0  = blockIdx.x * 128;
  const int mA  = g_modeA;
  const int mW  = g_modeW;
  int acc[8][8];
  #pragma unroll
  for (int i = 0; i < 8; i++)
    #pragma unroll
    for (int j = 0; j < 8; j++) acc[i][j] = 0;
  const int kq = tid >> 5;
  const int ng = tid & 31;
  for (int kc = 0; kc < KDIM / 64; kc++) {
    __syncthreads();
    #pragma unroll
    for (int rep = 0; rep < 2; rep++) {
      const int idx = tid + 256 * rep;
      const int row = idx >> 2;
      const int c   = idx & 3;
      const size_t e = (size_t)(m0 + row) * KDIM + kc * 64 + c * 16;
      uint32_t* d = (uint32_t*)&sa[row][c * 16];
      #pragma unroll
      for (int w4 = 0; w4 < 4; w4++) d[w4] = pack4(A, e + w4 * 4, mA);
    }
    #pragma unroll
    for (int rep = 0; rep < 2; rep++) {
      uint32_t w[4];
      #pragma unroll
      for (int i = 0; i < 4; i++)
        w[i] = pack4(W, (size_t)(kc * 64 + rep * 32 + kq * 4 + i) * NDIM + n0 + ng * 4, mW);
      #pragma unroll
      for (int c = 0; c < 4; c++) {
        const uint32_t tw = ((w[0] >> (8 * c)) & 0xFF)
                          | (((w[1] >> (8 * c)) & 0xFF) << 8)
                          | (((w[2] >> (8 * c)) & 0xFF) << 16)
                          | (((w[3] >> (8 * c)) & 0xFF) << 24);
        *(uint32_t*)&swt[ng * 4 + c][(rep * 8 + kq) * 4] = tw;
      }
    }
    __syncthreads();
    #pragma unroll
    for (int kw = 0; kw < 16; kw++) {
      int aw[8], bw[8];
      #pragma unroll
      for (int mi = 0; mi < 8; mi++) aw[mi] = *(const int*)&sa[tm + mi * 16][kw * 4];
      #pragma unroll
      for (int ni = 0; ni < 8; ni++) bw[ni] = *(const int*)&swt[tn + ni * 16][kw * 4];
      #pragma unroll
      for (int mi = 0; mi < 8; mi++)
        #pragma unroll
        for (int ni = 0; ni < 8; ni++)
          acc[mi][ni] = __dp4a(aw[mi], bw[ni], acc[mi][ni]);
    }
  }
  const int mAs = g_modeAs, mWs = g_modeWs;
  float asf[8], wsf[8];
  #pragma unroll
  for (int mi = 0; mi < 8; mi++) asf[mi] = get_scale(As, m0 + tm + mi * 16, mAs);
  #pragma unroll
  for (int ni = 0; ni < 8; ni++) wsf[ni] = get_scale(Ws, n0 + tn + ni * 16, mWs);
  #pragma unroll
  for (int mi = 0; mi < 8; mi++) {
    const size_t rb = (size_t)(m0 + tm + mi * 16) * NDIM + n0;
    #pragma unroll
    for (int ni = 0; ni < 8; ni++) {
      const float v = ((float)acc[mi][ni] * asf[mi]) * wsf[ni];
      Out[rb + tn + ni * 16] = __half2float(__float2half(v));
    }
  }
}

} // namespace

extern "C" void kernel_launch(void* const* d_in, const int* in_sizes, int n_in,
                              void* d_out, int out_size) {
  const uint8_t* A  = (const uint8_t*)d_in[0];
  const uint8_t* As = (const uint8_t*)d_in[1];
  const uint8_t* W  = (const uint8_t*)d_in[2];
  const uint8_t* Ws = (const uint8_t*)d_in[3];
  for (int i = 0; i < n_in; i++) {
    const long long s = in_sizes[i];
    switch (s) {
      case 33554432LL: case 134217728LL: A  = (const uint8_t*)d_in[i]; break;
      case 16777216LL: case 67108864LL:  W  = (const uint8_t*)d_in[i]; break;
      case 8192LL:     case 32768LL:     As = (const uint8_t*)d_in[i]; break;
      case 4096LL:     case 16384LL:     Ws = (const uint8_t*)d_in[i]; break;
      default: break;
    }
  }
  float* out = (float*)d_out;

  probe_matrix<<<1, 128>>>(A, 0);
  probe_matrix<<<1, 128>>>(W, 1);
  probe_scale<<<1, 128>>>(As, 0);
  probe_scale<<<1, 128>>>(Ws, 1);

  static cudaError_t attr_rc = cudaFuncSetAttribute(
      int8_gemm_mma, cudaFuncAttributeMaxDynamicSharedMemorySize, SMEM_TOTAL);

  if (attr_rc == cudaSuccess) {
    repack_A<<<(int)(((size_t)MDIM * KDIM / 4) / 256), 256>>>(A);
    dim3 tg(NDIM / 128, KDIM / 128);
    repack_Wt<<<tg, 256>>>(W);
    dim3 grid(NDIM / BN, MDIM / BM);   // 32 x 32
    int8_gemm_mma<<<grid, 256, SMEM_TOTAL>>>(As, Ws, out);
  } else {
    dim3 grid(NDIM / 128, MDIM / 128);
    dp4a_gemm<<<grid, 256>>>(A, As, W, Ws, out);
  }
}

// round 16
// speedup vs baseline: 2.1520x; 1.0358x over previous
#include <cuda_runtime.h>
#include <cuda_fp16.h>
#include <cuda_bf16.h>
#include <cstdint>

// ============================================================================
// int8 GEMM + dequant:  out[m,n] = f32( fp16_round( acc * a_s[m] * w_s[n] ) )
//   M=8192, K=4096, N=4096
//
// R14: mma path passed (rel_err=0) at 1965us with 1 CTA/SM (147KB smem),
// 2 warps/SMSP, 2 syncs/k-iter. This round targets latency hiding:
//   - CTA tile 128x128x128, 3 stages, 96KB smem -> 2 CTAs/SM (4 warps/SMSP)
//   - one __syncthreads per k-iter (loads after compute; wait_group 1)
//   - probes fused into one launch
// Fallback dp4a kernel retained (guards the smem attribute opt-in).
// ============================================================================

namespace {

constexpr int MDIM = 8192;
constexpr int NDIM = 4096;
constexpr int KDIM = 4096;

__device__ int g_modeA;    // 0=int8 packed, 1=int32, 2=f32, 3=bf16, 4=f16
__device__ int g_modeW;
__device__ int g_modeAs;   // 0=f32, 1=bf16, 2=f16
__device__ int g_modeWs;

__device__ int8_t g_A [(size_t)MDIM * KDIM];   // 32 MB packed A
__device__ int8_t g_Wt[(size_t)NDIM * KDIM];   // 16 MB packed W^T (n-major, k-contig)

// ---------------- fused dtype probes (one launch, 4 blocks) ----------------
__global__ void probe_all(const uint8_t* __restrict__ A,
                          const uint8_t* __restrict__ W,
                          const uint8_t* __restrict__ As,
                          const uint8_t* __restrict__ Ws) {
  __shared__ int ok[4];
  const int tid = threadIdx.x;
  const int b   = blockIdx.x;
  if (tid < 4) ok[tid] = 1;
  __syncthreads();
  if (b < 2) {
    const uint8_t* buf = (b == 0) ? A : W;
    for (int i = tid; i < 1024; i += blockDim.x) {
      const int vi = ((const int*)buf)[i];
      if (vi < -128 || vi > 127) ok[0] = 0;
      const float vf = ((const float*)buf)[i];
      if (!(vf >= -128.f && vf <= 127.f && floorf(vf) == vf)) ok[1] = 0;
      const float vb = __bfloat162float(((const __nv_bfloat16*)buf)[i]);
      if (!(vb >= -128.f && vb <= 127.f && floorf(vb) == vb)) ok[2] = 0;
      const float vh = __half2float(((const __half*)buf)[i]);
      if (!(vh >= -128.f && vh <= 127.f && floorf(vh) == vh)) ok[3] = 0;
    }
    __syncthreads();
    if (tid == 0) {
      const int mode = ok[0] ? 1 : ok[1] ? 2 : ok[2] ? 3 : ok[3] ? 4 : 0;
      if (b == 0) g_modeA = mode; else g_modeW = mode;
    }
  } else {
    const uint8_t* buf = (b == 2) ? As : Ws;
    for (int i = tid; i < 512; i += blockDim.x) {
      const float vf = ((const float*)buf)[i];
      if (!(vf > 1e-4f && vf < 1.0f)) ok[0] = 0;
      const float vb = __bfloat162float(((const __nv_bfloat16*)buf)[i]);
      if (!(vb > 1e-4f && vb < 1.0f)) ok[1] = 0;
      const float vh = __half2float(((const __half*)buf)[i]);
      if (!(vh > 1e-4f && vh < 1.0f)) ok[2] = 0;
    }
    __syncthreads();
    if (tid == 0) {
      const int mode = ok[0] ? 0 : ok[1] ? 1 : 2;
      if (b == 2) g_modeAs = mode; else g_modeWs = mode;
    }
  }
}

__device__ __forceinline__ float get_scale(const uint8_t* base, int idx, int mode) {
  if (mode == 0) return ((const float*)base)[idx];
  if (mode == 1) return __bfloat162float(((const __nv_bfloat16*)base)[idx]);
  return __half2float(((const __half*)base)[idx]);
}
__device__ __forceinline__ int8_t get_i8(const uint8_t* base, size_t e, int mode) {
  if (mode == 0) return ((const int8_t*)base)[e];
  if (mode == 1) return (int8_t)((const int*)base)[e];
  if (mode == 2) return (int8_t)(int)((const float*)base)[e];
  if (mode == 3) return (int8_t)(int)__bfloat162float(((const __nv_bfloat16*)base)[e]);
  return (int8_t)(int)__half2float(((const __half*)base)[e]);
}
__device__ __forceinline__ uint32_t pack4(const uint8_t* base, size_t e, int mode) {
  if (mode == 0) return *(const uint32_t*)(base + e);
  uint32_t r = 0;
  #pragma unroll
  for (int i = 0; i < 4; i++)
    r |= ((uint32_t)(uint8_t)get_i8(base, e + i, mode)) << (8 * i);
  return r;
}

// ---------------- repack kernels ----------------
__global__ void __launch_bounds__(256) repack_A(const uint8_t* __restrict__ A) {
  const int mode = g_modeA;
  const size_t idx = (size_t)blockIdx.x * 256 + threadIdx.x;   // word index
  ((uint32_t*)g_A)[idx] = pack4(A, idx * 4, mode);
}

__global__ void __launch_bounds__(256) repack_Wt(const uint8_t* __restrict__ W) {
  __shared__ int8_t tile[128][132];
  const int mode = g_modeW;
  const int n0 = blockIdx.x * 128;
  const int k0 = blockIdx.y * 128;
  const int tid = threadIdx.x;
  for (int idx = tid; idx < 128 * 128; idx += 256) {
    const int k = idx >> 7, n = idx & 127;
    tile[k][n] = get_i8(W, (size_t)(k0 + k) * NDIM + n0 + n, mode);
  }
  __syncthreads();
  for (int idx = tid; idx < 128 * 32; idx += 256) {
    const int n = idx >> 5, kw = idx & 31;
    const uint32_t v = (uint32_t)(uint8_t)tile[kw * 4 + 0][n]
                     | ((uint32_t)(uint8_t)tile[kw * 4 + 1][n] << 8)
                     | ((uint32_t)(uint8_t)tile[kw * 4 + 2][n] << 16)
                     | ((uint32_t)(uint8_t)tile[kw * 4 + 3][n] << 24);
    *(uint32_t*)(g_Wt + (size_t)(n0 + n) * KDIM + k0 + kw * 4) = v;
  }
}

// ---------------- tensor-core GEMM ----------------
constexpr int BM = 128, BN = 128, BK = 128;
constexpr int STAGES = 3;
constexpr int NKI = KDIM / BK;             // 32
constexpr int ASTAGE = BM * BK;            // 16384
constexpr int BSTAGE = BN * BK;            // 16384
constexpr int STAGE  = ASTAGE + BSTAGE;    // 32768
constexpr int SMEM_TOTAL = STAGES * STAGE; // 98304 -> 2 CTAs/SM

__device__ __forceinline__ uint32_t smem_u32(const void* p) {
  uint32_t a;
  asm("{ .reg .u64 t; cvta.to.shared.u64 t, %1; cvt.u32.u64 %0, t; }"
      : "=r"(a) : "l"(p));
  return a;
}
__device__ __forceinline__ void cp16(uint32_t s, const void* g) {
  asm volatile("cp.async.cg.shared.global [%0], [%1], 16;" :: "r"(s), "l"(g) : "memory");
}
__device__ __forceinline__ void cp_commit() {
  asm volatile("cp.async.commit_group;" ::: "memory");
}
__device__ __forceinline__ void cp_wait1() {
  asm volatile("cp.async.wait_group 1;" ::: "memory");
}
__device__ __forceinline__ void ldm4(uint32_t* r, uint32_t a) {
  asm volatile("ldmatrix.sync.aligned.m8n8.x4.shared.b16 {%0,%1,%2,%3}, [%4];"
               : "=r"(r[0]), "=r"(r[1]), "=r"(r[2]), "=r"(r[3]) : "r"(a));
}
__device__ __forceinline__ void mma_s8(int* d, const uint32_t* a, const uint32_t* b) {
  asm volatile(
      "mma.sync.aligned.m16n8k32.row.col.s32.s8.s8.s32 "
      "{%0,%1,%2,%3}, {%4,%5,%6,%7}, {%8,%9}, {%0,%1,%2,%3};"
      : "+r"(d[0]), "+r"(d[1]), "+r"(d[2]), "+r"(d[3])
      : "r"(a[0]), "r"(a[1]), "r"(a[2]), "r"(a[3]), "r"(b[0]), "r"(b[1]));
}

__global__ void __launch_bounds__(256, 2)
int8_gemm_mma(const uint8_t* __restrict__ As,
              const uint8_t* __restrict__ Ws,
              float*         __restrict__ Out)
{
  extern __shared__ uint8_t smem[];
  const uint32_t sb = smem_u32(smem);
  const int tid  = threadIdx.x;
  const int wid  = tid >> 5;
  const int lane = tid & 31;

  const int m0 = blockIdx.y * BM;
  const int n0 = blockIdx.x * BN;
  const int mw = (wid >> 1) * 32;   // 4 m-warps
  const int nw = (wid & 1)  * 64;   // 2 n-warps

  // producer: 16B chunk 0..7, base row 0..31
  const int pc = tid & 7;
  const int pr = tid >> 3;
  const int8_t* gA = g_A  + (size_t)(m0 + pr) * KDIM + pc * 16;
  const int8_t* gB = g_Wt + (size_t)(n0 + pr) * KDIM + pc * 16;

  auto load_stage = [&](int ki, int slot) {
    const uint32_t sa = sb + slot * STAGE;
    const uint32_t sB = sa + ASTAGE;
    #pragma unroll
    for (int j = 0; j < 4; j++) {
      const int r = pr + 32 * j;
      const uint32_t sw = r * 128 + (((pc ^ (r & 7)) & 7) << 4);
      cp16(sa + sw, gA + ki * BK + (size_t)(32 * j) * KDIM);
      cp16(sB + sw, gB + ki * BK + (size_t)(32 * j) * KDIM);
    }
  };

  #pragma unroll
  for (int s = 0; s < STAGES - 1; s++) { load_stage(s, s); cp_commit(); }

  int acc[2][8][4];
  #pragma unroll
  for (int mf = 0; mf < 2; mf++)
    #pragma unroll
    for (int nf = 0; nf < 8; nf++)
      #pragma unroll
      for (int i = 0; i < 4; i++) acc[mf][nf][i] = 0;

  const int lrow  = lane & 15;
  const int lchnk = lane >> 4;

  for (int ki = 0; ki < NKI; ki++) {
    cp_wait1();            // stage ki resident (1 newer group pending)
    __syncthreads();       // also orders: prior iter's reads before this iter's writes

    const uint32_t abase = sb + (ki % STAGES) * STAGE;
    const uint32_t bbase = abase + ASTAGE;

    #pragma unroll
    for (int ks = 0; ks < 4; ks++) {
      const int c = ks * 2 + lchnk;
      uint32_t af[2][4];
      #pragma unroll
      for (int mf = 0; mf < 2; mf++) {
        const int r = mw + mf * 16 + lrow;
        ldm4(af[mf], abase + r * 128 + (((c ^ (r & 7)) & 7) << 4));
      }
      uint32_t bf[8][2];
      #pragma unroll
      for (int nf2 = 0; nf2 < 4; nf2++) {
        uint32_t r4[4];
        const int r = nw + nf2 * 16 + lrow;
        ldm4(r4, bbase + r * 128 + (((c ^ (r & 7)) & 7) << 4));
        bf[2 * nf2][0]     = r4[0]; bf[2 * nf2][1]     = r4[2];
        bf[2 * nf2 + 1][0] = r4[1]; bf[2 * nf2 + 1][1] = r4[3];
      }
      #pragma unroll
      for (int mf = 0; mf < 2; mf++)
        #pragma unroll
        for (int nf = 0; nf < 8; nf++)
          mma_s8(acc[mf][nf], af[mf], bf[nf]);
    }

    // issue next stage AFTER compute: all warps passed the barrier above,
    // so last iter's readers of this slot are done. One sync per iter.
    if (ki + STAGES - 1 < NKI)
      load_stage(ki + STAGES - 1, (ki + STAGES - 1) % STAGES);
    cp_commit();
  }

  // epilogue: dequant (reference order), fp16-round, f32 store
  const int mAs = g_modeAs, mWs = g_modeWs;
  float ws[8][2];
  #pragma unroll
  for (int nf = 0; nf < 8; nf++) {
    const int c = n0 + nw + nf * 8 + (lane & 3) * 2;
    ws[nf][0] = get_scale(Ws, c,     mWs);
    ws[nf][1] = get_scale(Ws, c + 1, mWs);
  }
  #pragma unroll
  for (int mf = 0; mf < 2; mf++) {
    const int r = m0 + mw + mf * 16 + (lane >> 2);
    const float as0 = get_scale(As, r,     mAs);
    const float as1 = get_scale(As, r + 8, mAs);
    float* out0 = Out + (size_t)r * NDIM + n0 + nw + (lane & 3) * 2;
    float* out1 = out0 + (size_t)8 * NDIM;
    #pragma unroll
    for (int nf = 0; nf < 8; nf++) {
      float2 v0, v1;
      v0.x = __half2float(__float2half(((float)acc[mf][nf][0] * as0) * ws[nf][0]));
      v0.y = __half2float(__float2half(((float)acc[mf][nf][1] * as0) * ws[nf][1]));
      v1.x = __half2float(__float2half(((float)acc[mf][nf][2] * as1) * ws[nf][0]));
      v1.y = __half2float(__float2half(((float)acc[mf][nf][3] * as1) * ws[nf][1]));
      *(float2*)(out0 + nf * 8) = v0;
      *(float2*)(out1 + nf * 8) = v1;
    }
  }
}

// ---------------- dp4a fallback (known-good R13 path) ----------------
__global__ void __launch_bounds__(256)
dp4a_gemm(const uint8_t* __restrict__ A,
          const uint8_t* __restrict__ As,
          const uint8_t* __restrict__ W,
          const uint8_t* __restrict__ Ws,
          float*         __restrict__ Out)
{
  __shared__ int8_t sa [128][68];
  __shared__ int8_t swt[128][68];
  const int tid = threadIdx.x;
  const int tn  = tid & 15;
  const int tm  = tid >> 4;
  const int m0  = blockIdx.y * 128;
  const int n0  = blockIdx.x * 128;
  const int mA  = g_modeA;
  const int mW  = g_modeW;
  int acc[8][8];
  #pragma unroll
  for (int i = 0; i < 8; i++)
    #pragma unroll
    for (int j = 0; j < 8; j++) acc[i][j] = 0;
  const int kq = tid >> 5;
  const int ng = tid & 31;
  for (int kc = 0; kc < KDIM / 64; kc++) {
    __syncthreads();
    #pragma unroll
    for (int rep = 0; rep < 2; rep++) {
      const int idx = tid + 256 * rep;
      const int row = idx >> 2;
      const int c   = idx & 3;
      const size_t e = (size_t)(m0 + row) * KDIM + kc * 64 + c * 16;
      uint32_t* d = (uint32_t*)&sa[row][c * 16];
      #pragma unroll
      for (int w4 = 0; w4 < 4; w4++) d[w4] = pack4(A, e + w4 * 4, mA);
    }
    #pragma unroll
    for (int rep = 0; rep < 2; rep++) {
      uint32_t w[4];
      #pragma unroll
      for (int i = 0; i < 4; i++)
        w[i] = pack4(W, (size_t)(kc * 64 + rep * 32 + kq * 4 + i) * NDIM + n0 + ng * 4, mW);
      #pragma unroll
      for (int c = 0; c < 4; c++) {
        const uint32_t tw = ((w[0] >> (8 * c)) & 0xFF)
                          | (((w[1] >> (8 * c)) & 0xFF) << 8)
                          | (((w[2] >> (8 * c)) & 0xFF) << 16)
                          | (((w[3] >> (8 * c)) & 0xFF) << 24);
        *(uint32_t*)&swt[ng * 4 + c][(rep * 8 + kq) * 4] = tw;
      }
    }
    __syncthreads();
    #pragma unroll
    for (int kw = 0; kw < 16; kw++) {
      int aw[8], bw[8];
      #pragma unroll
      for (int mi = 0; mi < 8; mi++) aw[mi] = *(const int*)&sa[tm + mi * 16][kw * 4];
      #pragma unroll
      for (int ni = 0; ni < 8; ni++) bw[ni] = *(const int*)&swt[tn + ni * 16][kw * 4];
      #pragma unroll
      for (int mi = 0; mi < 8; mi++)
        #pragma unroll
        for (int ni = 0; ni < 8; ni++)
          acc[mi][ni] = __dp4a(aw[mi], bw[ni], acc[mi][ni]);
    }
  }
  const int mAs = g_modeAs, mWs = g_modeWs;
  float asf[8], wsf[8];
  #pragma unroll
  for (int mi = 0; mi < 8; mi++) asf[mi] = get_scale(As, m0 + tm + mi * 16, mAs);
  #pragma unroll
  for (int ni = 0; ni < 8; ni++) wsf[ni] = get_scale(Ws, n0 + tn + ni * 16, mWs);
  #pragma unroll
  for (int mi = 0; mi < 8; mi++) {
    const size_t rb = (size_t)(m0 + tm + mi * 16) * NDIM + n0;
    #pragma unroll
    for (int ni = 0; ni < 8; ni++) {
      const float v = ((float)acc[mi][ni] * asf[mi]) * wsf[ni];
      Out[rb + tn + ni * 16] = __half2float(__float2half(v));
    }
  }
}

} // namespace

extern "C" void kernel_launch(void* const* d_in, const int* in_sizes, int n_in,
                              void* d_out, int out_size) {
  const uint8_t* A  = (const uint8_t*)d_in[0];
  const uint8_t* As = (const uint8_t*)d_in[1];
  const uint8_t* W  = (const uint8_t*)d_in[2];
  const uint8_t* Ws = (const uint8_t*)d_in[3];
  for (int i = 0; i < n_in; i++) {
    const long long s = in_sizes[i];
    switch (s) {
      case 33554432LL: case 134217728LL: A  = (const uint8_t*)d_in[i]; break;
      case 16777216LL: case 67108864LL:  W  = (const uint8_t*)d_in[i]; break;
      case 8192LL:     case 32768LL:     As = (const uint8_t*)d_in[i]; break;
      case 4096LL:     case 16384LL:     Ws = (const uint8_t*)d_in[i]; break;
      default: break;
    }
  }
  float* out = (float*)d_out;

  probe_all<<<4, 128>>>(A, W, As, Ws);

  static cudaError_t attr_rc = cudaFuncSetAttribute(
      int8_gemm_mma, cudaFuncAttributeMaxDynamicSharedMemorySize, SMEM_TOTAL);

  if (attr_rc == cudaSuccess) {
    repack_A<<<(int)(((size_t)MDIM * KDIM / 4) / 256), 256>>>(A);
    dim3 tg(NDIM / 128, KDIM / 128);
    repack_Wt<<<tg, 256>>>(W);
    dim3 grid(NDIM / BN, MDIM / BM);   // 32 x 64
    int8_gemm_mma<<<grid, 256, SMEM_TOTAL>>>(As, Ws, out);
  } else {
    dim3 grid(NDIM / 128, MDIM / 128);
    dp4a_gemm<<<grid, 256>>>(A, As, W, Ws, out);
  }
}